// round 15
// baseline (speedup 1.0000x reference)
#include <cuda_runtime.h>
#include <cuda_bf16.h>
#include <math.h>

#define BB 4096
#define SS 512
#define EE 64
#define MM 16
#define OUTD 64
#define NSTEPS 5

// Scratch: memories transposed per batch: g_memT[b*MM*SS + m*SS + s]
__device__ float g_memT[(size_t)BB * MM * SS];

// ---------------- bf16 pack/split helpers ----------------
__device__ __forceinline__ unsigned int packbf(float lo, float hi) {
    __nv_bfloat162 p = __floats2bfloat162_rn(lo, hi);   // .x -> low 16 bits
    return *reinterpret_cast<unsigned int*>(&p);
}
__device__ __forceinline__ void split2(float v0, float v1,
                                       unsigned int& ph, unsigned int& pl) {
    ph = packbf(v0, v1);
    float f0 = __uint_as_float(ph << 16);
    float f1 = __uint_as_float(ph & 0xffff0000u);
    pl = packbf(v0 - f0, v1 - f1);
}

__device__ __forceinline__ void mma16816(float* c, const unsigned int* a, uint2 b) {
    asm("mma.sync.aligned.m16n8k16.row.col.f32.bf16.bf16.f32 "
        "{%0,%1,%2,%3}, {%4,%5,%6,%7}, {%8,%9}, {%0,%1,%2,%3};"
        : "+f"(c[0]), "+f"(c[1]), "+f"(c[2]), "+f"(c[3])
        : "r"(a[0]), "r"(a[1]), "r"(a[2]), "r"(a[3]), "r"(b.x), "r"(b.y));
}

// ---------------- cp.async helpers ----------------
__device__ __forceinline__ void cp_async16(void* smem_ptr, const void* gptr) {
    unsigned int saddr = (unsigned int)__cvta_generic_to_shared(smem_ptr);
    asm volatile("cp.async.cg.shared.global [%0], [%1], 16;"
                 :: "r"(saddr), "l"(gptr));
}
__device__ __forceinline__ void cp_commit() {
    asm volatile("cp.async.commit_group;");
}
template <int N>
__device__ __forceinline__ void cp_wait() {
    asm volatile("cp.async.wait_group %0;" :: "n"(N));
}

// B-fragment builder (same math as the old prep_kernel)
__device__ __forceinline__ uint2 make_bfrag(const float* __restrict__ w,
                                            int K, int n, int kbase, int t, int lo)
{
    float a0 = w[n * K + kbase + 2 * t];
    float a1 = w[n * K + kbase + 2 * t + 1];
    float a8 = w[n * K + kbase + 2 * t + 8];
    float a9 = w[n * K + kbase + 2 * t + 9];
    if (lo) {
        a0 -= __bfloat162float(__float2bfloat16(a0));
        a1 -= __bfloat162float(__float2bfloat16(a1));
        a8 -= __bfloat162float(__float2bfloat16(a8));
        a9 -= __bfloat162float(__float2bfloat16(a9));
    }
    uint2 r;
    r.x = packbf(a0, a1);
    r.y = packbf(a8, a9);
    return r;
}

// ---------------------------------------------------------------------------
// Kernel 1: reading MLP on tensor cores (bf16 3-term split, fp32 accum).
// cp.async double-buffered staging (R11/R13-proven). Self-contained:
// B-fragments computed per-CTA into smem from the raw weights (no prep).
// ---------------------------------------------------------------------------
#define XROW 68                       // padded smem row stride (floats)
#define XSTAGE (128 * XROW)           // floats per stage
#define SMEM_DYN (14336 + 384 + 2 * XSTAGE * 4)

__global__ void __launch_bounds__(256) mem_mlp_kernel(
    const float* __restrict__ x,
    const float* __restrict__ rw1, const float* __restrict__ b1,
    const float* __restrict__ rw2, const float* __restrict__ b2,
    const float* __restrict__ rw3, const float* __restrict__ b3)
{
    extern __shared__ char dynsm[];
    uint2* sW  = (uint2*)dynsm;                       // 14336 B (56*32 uint2)
    float* sb1 = (float*)(dynsm + 14336);             // 32
    float* sb2 = sb1 + 32;                            // 32
    float* sb3 = sb2 + 32;                            // 16
    float* xs  = (float*)(dynsm + 14336 + 384);       // 2 stages

    int tid = threadIdx.x;
    int lane = tid & 31, warp = tid >> 5;
    int g = lane >> 2, t = lane & 3;

    // issue the first x stage before anything else (hide DRAM latency under
    // the frag construction below)
    auto issue_stage = [&](int it) {
        size_t base_row = ((size_t)it * 16384 + blockIdx.x * 8) * 16;
        const float* gx = x + base_row * 64;
        float* dst = xs + (it & 1) * XSTAGE;
        #pragma unroll
        for (int i = tid; i < 2048; i += 256) {
            int r = i >> 4, cch = i & 15;
            cp_async16(dst + r * XROW + cch * 4, gx + r * 64 + cch * 4);
        }
        cp_commit();
    };
    issue_stage(0);

    // build B-fragments in smem (one-time, ~7 entries per thread)
    for (int i = tid; i < 56 * 32; i += 256) {
        int li = i & 31, fid = i >> 5;
        int gg = li >> 2, tt = li & 3;
        uint2 f;
        if (fid < 32) {
            int lo = (fid >= 16);
            int c  = (fid & 15) >> 2, n4 = fid & 3;
            f = make_bfrag(rw1, 64, n4 * 8 + gg, c * 16, tt, lo);
        } else if (fid < 48) {
            int lo = (fid >= 40);
            int c  = ((fid - 32) & 7) >> 2, n4 = fid & 3;
            f = make_bfrag(rw2, 32, n4 * 8 + gg, c * 16, tt, lo);
        } else {
            int lo = (fid >= 52);
            int c  = ((fid - 48) & 3) >> 1, n2 = fid & 1;
            f = make_bfrag(rw3, 32, n2 * 8 + gg, c * 16, tt, lo);
        }
        sW[fid * 32 + li] = f;
    }
    if (tid < 32) { sb1[tid] = b1[tid]; sb2[tid] = b2[tid]; }
    if (tid < 16) sb3[tid] = b3[tid];
    __syncthreads();

    #pragma unroll 1
    for (int it = 0; it < 8; it++) {
        if (it + 1 < 8) {
            issue_stage(it + 1);
            cp_wait<1>();
        } else {
            cp_wait<0>();
        }
        __syncthreads();

        const float* xbuf = xs + (it & 1) * XSTAGE;
        const float* xr0 = xbuf + (warp * 16 + g) * XROW;
        const float* xr1 = xr0 + 8 * XROW;

        unsigned int Ah[4][4], Al[4][4];
        #pragma unroll
        for (int c = 0; c < 4; c++) {
            float2 v00 = *(const float2*)(xr0 + c * 16 + 2 * t);
            float2 v01 = *(const float2*)(xr0 + c * 16 + 2 * t + 8);
            float2 v10 = *(const float2*)(xr1 + c * 16 + 2 * t);
            float2 v11 = *(const float2*)(xr1 + c * 16 + 2 * t + 8);
            split2(v00.x, v00.y, Ah[c][0], Al[c][0]);
            split2(v10.x, v10.y, Ah[c][1], Al[c][1]);
            split2(v01.x, v01.y, Ah[c][2], Al[c][2]);
            split2(v11.x, v11.y, Ah[c][3], Al[c][3]);
        }

        float C1[4][4];
        #pragma unroll
        for (int n4 = 0; n4 < 4; n4++) {
            float q0 = sb1[n4 * 8 + 2 * t], q1 = sb1[n4 * 8 + 2 * t + 1];
            C1[n4][0] = q0; C1[n4][1] = q1; C1[n4][2] = q0; C1[n4][3] = q1;
        }
        #pragma unroll
        for (int c = 0; c < 4; c++) {
            #pragma unroll
            for (int n4 = 0; n4 < 4; n4++) {
                uint2 wh = sW[(c * 4 + n4) * 32 + lane];
                uint2 wl = sW[(16 + c * 4 + n4) * 32 + lane];
                mma16816(C1[n4], Ah[c], wh);
                mma16816(C1[n4], Al[c], wh);
                mma16816(C1[n4], Ah[c], wl);
            }
        }

        unsigned int A2h[2][4], A2l[2][4];
        #pragma unroll
        for (int cc = 0; cc < 2; cc++) {
            #pragma unroll
            for (int h = 0; h < 2; h++) {
                float p0 = fmaxf(C1[2*cc][2*h],     0.f);
                float p1 = fmaxf(C1[2*cc][2*h + 1], 0.f);
                split2(p0, p1, A2h[cc][h], A2l[cc][h]);
                float q0 = fmaxf(C1[2*cc+1][2*h],     0.f);
                float q1 = fmaxf(C1[2*cc+1][2*h + 1], 0.f);
                split2(q0, q1, A2h[cc][2 + h], A2l[cc][2 + h]);
            }
        }

        float C2[4][4];
        #pragma unroll
        for (int n4 = 0; n4 < 4; n4++) {
            float q0 = sb2[n4 * 8 + 2 * t], q1 = sb2[n4 * 8 + 2 * t + 1];
            C2[n4][0] = q0; C2[n4][1] = q1; C2[n4][2] = q0; C2[n4][3] = q1;
        }
        #pragma unroll
        for (int c = 0; c < 2; c++) {
            #pragma unroll
            for (int n4 = 0; n4 < 4; n4++) {
                uint2 wh = sW[(32 + c * 4 + n4) * 32 + lane];
                uint2 wl = sW[(40 + c * 4 + n4) * 32 + lane];
                mma16816(C2[n4], A2h[c], wh);
                mma16816(C2[n4], A2l[c], wh);
                mma16816(C2[n4], A2h[c], wl);
            }
        }

        unsigned int A3h[2][4], A3l[2][4];
        #pragma unroll
        for (int cc = 0; cc < 2; cc++) {
            #pragma unroll
            for (int h = 0; h < 2; h++) {
                float p0 = fmaxf(C2[2*cc][2*h],     0.f);
                float p1 = fmaxf(C2[2*cc][2*h + 1], 0.f);
                split2(p0, p1, A3h[cc][h], A3l[cc][h]);
                float q0 = fmaxf(C2[2*cc+1][2*h],     0.f);
                float q1 = fmaxf(C2[2*cc+1][2*h + 1], 0.f);
                split2(q0, q1, A3h[cc][2 + h], A3l[cc][2 + h]);
            }
        }

        float C3[2][4];
        #pragma unroll
        for (int n2 = 0; n2 < 2; n2++) {
            float q0 = sb3[n2 * 8 + 2 * t], q1 = sb3[n2 * 8 + 2 * t + 1];
            C3[n2][0] = q0; C3[n2][1] = q1; C3[n2][2] = q0; C3[n2][3] = q1;
        }
        #pragma unroll
        for (int c = 0; c < 2; c++) {
            #pragma unroll
            for (int n2 = 0; n2 < 2; n2++) {
                uint2 wh = sW[(48 + c * 2 + n2) * 32 + lane];
                uint2 wl = sW[(52 + c * 2 + n2) * 32 + lane];
                mma16816(C3[n2], A3h[c], wh);
                mma16816(C3[n2], A3l[c], wh);
                mma16816(C3[n2], A3h[c], wl);
            }
        }

        int tile = it * 16384 + blockIdx.x * 8 + warp;
        int R  = tile * 16;
        int b  = R >> 9;
        int s0 = (R & 511) + g;
        int s1 = s0 + 8;
        float* outb = g_memT + (size_t)b * 8192;
        #pragma unroll
        for (int n2 = 0; n2 < 2; n2++) {
            int m0 = n2 * 8 + 2 * t;
            outb[m0 * 512 + s0]       = C3[n2][0];
            outb[(m0 + 1) * 512 + s0] = C3[n2][1];
            outb[m0 * 512 + s1]       = C3[n2][2];
            outb[(m0 + 1) * 512 + s1] = C3[n2][3];
        }
        __syncthreads();
    }
}

// ---------------------------------------------------------------------------
// Kernel 2: 128 threads / 4 warps per batch — R13 structure; weights read
// DIRECTLY from the original row-major arrays (no transposed scratch, no prep):
//   wg[k] = whh[tid*32+k], wq[k] = pw[(tid&15)*32+k], w1/w2/w3 rows likewise.
// ---------------------------------------------------------------------------
__device__ __forceinline__ float sigmoidf_(float x) {
    return 1.f / (1.f + __expf(-x));
}

__global__ void __launch_bounds__(128) step_kernel(
    const int*   __restrict__ lengths,
    const float* __restrict__ whh,   // (128,32) row-major
    const float* __restrict__ bih,   // 128
    const float* __restrict__ bhh,   // 128
    const float* __restrict__ pw,    // (16,32)
    const float* __restrict__ pb_,   // 16
    const float* __restrict__ w1,    // (32,32)
    const float* __restrict__ b1,    // 32
    const float* __restrict__ w2,    // (32,32)
    const float* __restrict__ b2,    // 32
    const float* __restrict__ w3,    // (64,32)
    const float* __restrict__ b3,    // 64
    const float* __restrict__ esv_,  // 64
    float*       __restrict__ out)   // (B,64)
{
    __shared__ __align__(16) float memT[MM * SS];   // 32 KB [m*512+s]
    __shared__ float qst[32];
    __shared__ float hst[32];
    __shared__ float red[8 + 64];
    __shared__ float x1s[32], x2s[32];
    __shared__ float gates[128];

    const unsigned FULL = 0xffffffffu;
    int b    = blockIdx.x;
    int tid  = threadIdx.x;
    int lane = tid & 31;
    int warp = tid >> 5;

    {
        const float4* gm = (const float4*)(g_memT + (size_t)b * (MM * SS));
        float4* dst = (float4*)memT;
        #pragma unroll
        for (int i = tid; i < 2048; i += 128) dst[i] = gm[i];
    }
    if (tid < 32) qst[tid] = 0.f;

    int len  = lengths[b];
    int slen = (len > 0) ? len : 1;

    float bsr = __ldg(bih + tid) + __ldg(bhh + tid);
    float c   = 0.f;

    // preload loop-invariant weight rows (vectorized float4 global loads)
    float wg[32];
    {
        const float4* wr = (const float4*)(whh + tid * 32);
        #pragma unroll
        for (int k4 = 0; k4 < 8; k4++) {
            float4 v = __ldg(wr + k4);
            wg[4*k4] = v.x; wg[4*k4+1] = v.y; wg[4*k4+2] = v.z; wg[4*k4+3] = v.w;
        }
    }
    float wq[32];
    {
        const float4* wr = (const float4*)(pw + (tid & 15) * 32);
        #pragma unroll
        for (int k4 = 0; k4 < 8; k4++) {
            float4 v = __ldg(wr + k4);
            wq[4*k4] = v.x; wq[4*k4+1] = v.y; wq[4*k4+2] = v.z; wq[4*k4+3] = v.w;
        }
    }
    float pbr = pb_[tid & 15];
    __syncthreads();

    const float4* memT4 = (const float4*)memT;

    #pragma unroll 1
    for (int step = 0; step < NSTEPS; step++) {
        float ga = bsr;
        #pragma unroll
        for (int k = 0; k < 32; k++)
            ga = fmaf(qst[k], wg[k], ga);
        gates[tid] = ga;
        __syncthreads();

        if (tid < 32) {
            float ig = sigmoidf_(gates[tid]);
            float fg = sigmoidf_(gates[32 + tid]);
            float gg = tanhf(gates[64 + tid]);
            float og = sigmoidf_(gates[96 + tid]);
            c = fmaf(fg, c, ig * gg);
            hst[tid] = og * tanhf(c);
        }
        __syncthreads();

        if (tid < 16) {
            float aq = pbr;
            #pragma unroll
            for (int k = 0; k < 32; k++)
                aq = fmaf(hst[k], wq[k], aq);
            qst[tid] = aq;
        }
        __syncthreads();

        int base = lane + 32 * warp;
        float4 acc = make_float4(0.f, 0.f, 0.f, 0.f);
        #pragma unroll
        for (int m = 0; m < 16; m++) {
            float4 v = memT4[m * 128 + base];
            float q = qst[m];
            acc.x = fmaf(q, v.x, acc.x);
            acc.y = fmaf(q, v.y, acc.y);
            acc.z = fmaf(q, v.z, acc.z);
            acc.w = fmaf(q, v.w, acc.w);
        }
        int s = 4 * lane + 128 * warp;
        if (s     >= slen) acc.x = -1e30f;
        if (s + 1 >= slen) acc.y = -1e30f;
        if (s + 2 >= slen) acc.z = -1e30f;
        if (s + 3 >= slen) acc.w = -1e30f;

        float mx = fmaxf(fmaxf(acc.x, acc.y), fmaxf(acc.z, acc.w));
        #pragma unroll
        for (int off = 16; off; off >>= 1)
            mx = fmaxf(mx, __shfl_xor_sync(FULL, mx, off));
        if (lane == 0) red[warp] = mx;
        __syncthreads();
        mx = fmaxf(fmaxf(red[0], red[1]), fmaxf(red[2], red[3]));

        float4 ex;
        ex.x = __expf(acc.x - mx);
        ex.y = __expf(acc.y - mx);
        ex.z = __expf(acc.z - mx);
        ex.w = __expf(acc.w - mx);
        float ssum = (ex.x + ex.y) + (ex.z + ex.w);
        #pragma unroll
        for (int off = 16; off; off >>= 1)
            ssum += __shfl_xor_sync(FULL, ssum, off);
        if (lane == 0) red[4 + warp] = ssum;

        float rm[16];
        #pragma unroll
        for (int m = 0; m < 16; m++) {
            float4 v = memT4[m * 128 + base];
            rm[m] = fmaf(ex.x, v.x, fmaf(ex.y, v.y, fmaf(ex.z, v.z, ex.w * v.w)));
        }
        #pragma unroll
        for (int m = 0; m < 16; m++) {
            #pragma unroll
            for (int off = 16; off; off >>= 1)
                rm[m] += __shfl_xor_sync(FULL, rm[m], off);
        }
        if (lane == 0) {
            #pragma unroll
            for (int m = 0; m < 16; m++) red[8 + warp * 16 + m] = rm[m];
        }
        __syncthreads();

        if (tid < 16) {
            float inv = 1.f / (((red[4] + red[5]) + (red[6] + red[7])));
            float rr = ((red[8 + tid] + red[24 + tid]) +
                        (red[40 + tid] + red[56 + tid]));
            qst[16 + tid] = rr * inv;
        }
        __syncthreads();
    }

    // ---- write MLP: weights read as direct rows (w[j][k], j = tid) ----
    if (tid < 32) {
        float acc = b1[tid];
        const float* wr = w1 + tid * 32;
        #pragma unroll
        for (int k = 0; k < 32; k++)
            acc = fmaf(qst[k], __ldg(wr + k), acc);
        x1s[tid] = fmaxf(acc, 0.f);
    }
    __syncthreads();
    if (tid < 32) {
        float acc = b2[tid];
        const float* wr = w2 + tid * 32;
        #pragma unroll
        for (int k = 0; k < 32; k++)
            acc = fmaf(x1s[k], __ldg(wr + k), acc);
        x2s[tid] = fmaxf(acc, 0.f);
    }
    __syncthreads();
    if (tid < 64) {
        float acc = b3[tid];
        const float* wr = w3 + tid * 32;
        #pragma unroll
        for (int k = 0; k < 32; k++)
            acc = fmaf(x2s[k], __ldg(wr + k), acc);
        out[(size_t)b * OUTD + tid] = (len > 0) ? acc : esv_[tid];
    }
}

// ---------------------------------------------------------------------------
extern "C" void kernel_launch(void* const* d_in, const int* in_sizes, int n_in,
                              void* d_out, int out_size)
{
    const float* input_set = (const float*)d_in[0];
    const int*   lengths   = (const int*)  d_in[1];
    const float* r_w1 = (const float*)d_in[2];
    const float* r_b1 = (const float*)d_in[3];
    const float* r_w2 = (const float*)d_in[4];
    const float* r_b2 = (const float*)d_in[5];
    const float* r_w3 = (const float*)d_in[6];
    const float* r_b3 = (const float*)d_in[7];
    // d_in[8] = lstm_wih (unused: LSTM input is identically zero)
    const float* lstm_whh = (const float*)d_in[9];
    const float* lstm_bih = (const float*)d_in[10];
    const float* lstm_bhh = (const float*)d_in[11];
    const float* proj_w   = (const float*)d_in[12];
    const float* proj_b   = (const float*)d_in[13];
    const float* w_w1 = (const float*)d_in[14];
    const float* w_b1 = (const float*)d_in[15];
    const float* w_w2 = (const float*)d_in[16];
    const float* w_b2 = (const float*)d_in[17];
    const float* w_w3 = (const float*)d_in[18];
    const float* w_b3 = (const float*)d_in[19];
    const float* esv  = (const float*)d_in[20];
    float* out = (float*)d_out;

    static int smem_set = 0;
    if (!smem_set) {
        cudaFuncSetAttribute(mem_mlp_kernel,
                             cudaFuncAttributeMaxDynamicSharedMemorySize,
                             SMEM_DYN);
        smem_set = 1;
    }

    mem_mlp_kernel<<<2048, 256, SMEM_DYN>>>(input_set,
                                            r_w1, r_b1, r_w2, r_b2, r_w3, r_b3);

    step_kernel<<<BB, 128>>>(lengths,
                             lstm_whh, lstm_bih, lstm_bhh,
                             proj_w, proj_b,
                             w_w1, w_b1, w_w2, w_b2, w_w3, w_b3,
                             esv, out);
}

// round 16
// speedup vs baseline: 1.2786x; 1.2786x over previous
#include <cuda_runtime.h>
#include <cuda_bf16.h>
#include <math.h>

#define BB 4096
#define SS 512
#define EE 64
#define MM 16
#define OUTD 64
#define NSTEPS 5

// Scratch: memories transposed per batch: g_memT[b*MM*SS + m*SS + s]
__device__ float g_memT[(size_t)BB * MM * SS];
// Pre-transposed small weights (k-major) for the recurrence phase
__device__ float g_whhT[32 * 128];   // [k][j]
__device__ float g_pwT [32 * 16];    // [k][m]
__device__ float g_w1T [32 * 32];    // [k][j]
__device__ float g_w2T [32 * 32];    // [k][j]
__device__ float g_w3T [32 * 64];    // [k][j]
__device__ float g_bsum[128];        // bih + bhh

// ---------------- bf16 pack/split helpers ----------------
__device__ __forceinline__ unsigned int packbf(float lo, float hi) {
    __nv_bfloat162 p = __floats2bfloat162_rn(lo, hi);   // .x -> low 16 bits
    return *reinterpret_cast<unsigned int*>(&p);
}
__device__ __forceinline__ void split2(float v0, float v1,
                                       unsigned int& ph, unsigned int& pl) {
    ph = packbf(v0, v1);
    float f0 = __uint_as_float(ph << 16);
    float f1 = __uint_as_float(ph & 0xffff0000u);
    pl = packbf(v0 - f0, v1 - f1);
}

__device__ __forceinline__ void mma16816(float* c, const unsigned int* a, uint2 b) {
    asm("mma.sync.aligned.m16n8k16.row.col.f32.bf16.bf16.f32 "
        "{%0,%1,%2,%3}, {%4,%5,%6,%7}, {%8,%9}, {%0,%1,%2,%3};"
        : "+f"(c[0]), "+f"(c[1]), "+f"(c[2]), "+f"(c[3])
        : "r"(a[0]), "r"(a[1]), "r"(a[2]), "r"(a[3]), "r"(b.x), "r"(b.y));
}

// ---------------- cp.async helpers ----------------
__device__ __forceinline__ void cp_async16(void* smem_ptr, const void* gptr) {
    unsigned int saddr = (unsigned int)__cvta_generic_to_shared(smem_ptr);
    asm volatile("cp.async.cg.shared.global [%0], [%1], 16;"
                 :: "r"(saddr), "l"(gptr));
}
__device__ __forceinline__ void cp_commit() {
    asm volatile("cp.async.commit_group;");
}
template <int N>
__device__ __forceinline__ void cp_wait() {
    asm volatile("cp.async.wait_group %0;" :: "n"(N));
}

// B-fragment builder
__device__ __forceinline__ uint2 make_bfrag(const float* __restrict__ w,
                                            int K, int n, int kbase, int t, int lo)
{
    float a0 = w[n * K + kbase + 2 * t];
    float a1 = w[n * K + kbase + 2 * t + 1];
    float a8 = w[n * K + kbase + 2 * t + 8];
    float a9 = w[n * K + kbase + 2 * t + 9];
    if (lo) {
        a0 -= __bfloat162float(__float2bfloat16(a0));
        a1 -= __bfloat162float(__float2bfloat16(a1));
        a8 -= __bfloat162float(__float2bfloat16(a8));
        a9 -= __bfloat162float(__float2bfloat16(a9));
    }
    uint2 r;
    r.x = packbf(a0, a1);
    r.y = packbf(a8, a9);
    return r;
}

// ---------------------------------------------------------------------------
// Kernel 0: minimal prep — ONLY the coalesced-weight transposes for step.
// ---------------------------------------------------------------------------
__global__ void prep_kernel(
    const float* __restrict__ whh, const float* __restrict__ bih,
    const float* __restrict__ bhh, const float* __restrict__ pw,
    const float* __restrict__ w1,  const float* __restrict__ w2,
    const float* __restrict__ w3)
{
    int gid = blockIdx.x * 128 + threadIdx.x;   // 4096 threads
    int nt  = gridDim.x * 128;
    for (int i = gid; i < 4096; i += nt) { int j = i >> 5, k = i & 31; g_whhT[k*128 + j] = whh[i]; }
    for (int i = gid; i < 512;  i += nt) { int m = i >> 5, k = i & 31; g_pwT [k*16  + m] = pw[i]; }
    for (int i = gid; i < 1024; i += nt) { int j = i >> 5, k = i & 31; g_w1T[k*32 + j] = w1[i];
                                           g_w2T[k*32 + j] = w2[i]; }
    for (int i = gid; i < 2048; i += nt) { int j = i >> 5, k = i & 31; g_w3T[k*64 + j] = w3[i]; }
    if (gid < 128) g_bsum[gid] = bih[gid] + bhh[gid];
}

// ---------------------------------------------------------------------------
// Kernel 1: reading MLP on tensor cores (bf16 3-term split, fp32 accum).
// Self-contained frag build + cp.async double-buffered staging (R15-proven).
// ---------------------------------------------------------------------------
#define XROW 68                       // padded smem row stride (floats)
#define XSTAGE (128 * XROW)           // floats per stage
#define SMEM_DYN (14336 + 384 + 2 * XSTAGE * 4)

__global__ void __launch_bounds__(256) mem_mlp_kernel(
    const float* __restrict__ x,
    const float* __restrict__ rw1, const float* __restrict__ b1,
    const float* __restrict__ rw2, const float* __restrict__ b2,
    const float* __restrict__ rw3, const float* __restrict__ b3)
{
    extern __shared__ char dynsm[];
    uint2* sW  = (uint2*)dynsm;                       // 14336 B (56*32 uint2)
    float* sb1 = (float*)(dynsm + 14336);             // 32
    float* sb2 = sb1 + 32;                            // 32
    float* sb3 = sb2 + 32;                            // 16
    float* xs  = (float*)(dynsm + 14336 + 384);       // 2 stages

    int tid = threadIdx.x;
    int lane = tid & 31, warp = tid >> 5;
    int g = lane >> 2, t = lane & 3;

    auto issue_stage = [&](int it) {
        size_t base_row = ((size_t)it * 16384 + blockIdx.x * 8) * 16;
        const float* gx = x + base_row * 64;
        float* dst = xs + (it & 1) * XSTAGE;
        #pragma unroll
        for (int i = tid; i < 2048; i += 256) {
            int r = i >> 4, cch = i & 15;
            cp_async16(dst + r * XROW + cch * 4, gx + r * 64 + cch * 4);
        }
        cp_commit();
    };
    issue_stage(0);

    // build B-fragments in smem (one-time)
    for (int i = tid; i < 56 * 32; i += 256) {
        int li = i & 31, fid = i >> 5;
        int gg = li >> 2, tt = li & 3;
        uint2 f;
        if (fid < 32) {
            int lo = (fid >= 16);
            int c  = (fid & 15) >> 2, n4 = fid & 3;
            f = make_bfrag(rw1, 64, n4 * 8 + gg, c * 16, tt, lo);
        } else if (fid < 48) {
            int lo = (fid >= 40);
            int c  = ((fid - 32) & 7) >> 2, n4 = fid & 3;
            f = make_bfrag(rw2, 32, n4 * 8 + gg, c * 16, tt, lo);
        } else {
            int lo = (fid >= 52);
            int c  = ((fid - 48) & 3) >> 1, n2 = fid & 1;
            f = make_bfrag(rw3, 32, n2 * 8 + gg, c * 16, tt, lo);
        }
        sW[fid * 32 + li] = f;
    }
    if (tid < 32) { sb1[tid] = b1[tid]; sb2[tid] = b2[tid]; }
    if (tid < 16) sb3[tid] = b3[tid];
    __syncthreads();

    #pragma unroll 1
    for (int it = 0; it < 8; it++) {
        if (it + 1 < 8) {
            issue_stage(it + 1);
            cp_wait<1>();
        } else {
            cp_wait<0>();
        }
        __syncthreads();

        const float* xbuf = xs + (it & 1) * XSTAGE;
        const float* xr0 = xbuf + (warp * 16 + g) * XROW;
        const float* xr1 = xr0 + 8 * XROW;

        unsigned int Ah[4][4], Al[4][4];
        #pragma unroll
        for (int c = 0; c < 4; c++) {
            float2 v00 = *(const float2*)(xr0 + c * 16 + 2 * t);
            float2 v01 = *(const float2*)(xr0 + c * 16 + 2 * t + 8);
            float2 v10 = *(const float2*)(xr1 + c * 16 + 2 * t);
            float2 v11 = *(const float2*)(xr1 + c * 16 + 2 * t + 8);
            split2(v00.x, v00.y, Ah[c][0], Al[c][0]);
            split2(v10.x, v10.y, Ah[c][1], Al[c][1]);
            split2(v01.x, v01.y, Ah[c][2], Al[c][2]);
            split2(v11.x, v11.y, Ah[c][3], Al[c][3]);
        }

        float C1[4][4];
        #pragma unroll
        for (int n4 = 0; n4 < 4; n4++) {
            float q0 = sb1[n4 * 8 + 2 * t], q1 = sb1[n4 * 8 + 2 * t + 1];
            C1[n4][0] = q0; C1[n4][1] = q1; C1[n4][2] = q0; C1[n4][3] = q1;
        }
        #pragma unroll
        for (int c = 0; c < 4; c++) {
            #pragma unroll
            for (int n4 = 0; n4 < 4; n4++) {
                uint2 wh = sW[(c * 4 + n4) * 32 + lane];
                uint2 wl = sW[(16 + c * 4 + n4) * 32 + lane];
                mma16816(C1[n4], Ah[c], wh);
                mma16816(C1[n4], Al[c], wh);
                mma16816(C1[n4], Ah[c], wl);
            }
        }

        unsigned int A2h[2][4], A2l[2][4];
        #pragma unroll
        for (int cc = 0; cc < 2; cc++) {
            #pragma unroll
            for (int h = 0; h < 2; h++) {
                float p0 = fmaxf(C1[2*cc][2*h],     0.f);
                float p1 = fmaxf(C1[2*cc][2*h + 1], 0.f);
                split2(p0, p1, A2h[cc][h], A2l[cc][h]);
                float q0 = fmaxf(C1[2*cc+1][2*h],     0.f);
                float q1 = fmaxf(C1[2*cc+1][2*h + 1], 0.f);
                split2(q0, q1, A2h[cc][2 + h], A2l[cc][2 + h]);
            }
        }

        float C2[4][4];
        #pragma unroll
        for (int n4 = 0; n4 < 4; n4++) {
            float q0 = sb2[n4 * 8 + 2 * t], q1 = sb2[n4 * 8 + 2 * t + 1];
            C2[n4][0] = q0; C2[n4][1] = q1; C2[n4][2] = q0; C2[n4][3] = q1;
        }
        #pragma unroll
        for (int c = 0; c < 2; c++) {
            #pragma unroll
            for (int n4 = 0; n4 < 4; n4++) {
                uint2 wh = sW[(32 + c * 4 + n4) * 32 + lane];
                uint2 wl = sW[(40 + c * 4 + n4) * 32 + lane];
                mma16816(C2[n4], A2h[c], wh);
                mma16816(C2[n4], A2l[c], wh);
                mma16816(C2[n4], A2h[c], wl);
            }
        }

        unsigned int A3h[2][4], A3l[2][4];
        #pragma unroll
        for (int cc = 0; cc < 2; cc++) {
            #pragma unroll
            for (int h = 0; h < 2; h++) {
                float p0 = fmaxf(C2[2*cc][2*h],     0.f);
                float p1 = fmaxf(C2[2*cc][2*h + 1], 0.f);
                split2(p0, p1, A3h[cc][h], A3l[cc][h]);
                float q0 = fmaxf(C2[2*cc+1][2*h],     0.f);
                float q1 = fmaxf(C2[2*cc+1][2*h + 1], 0.f);
                split2(q0, q1, A3h[cc][2 + h], A3l[cc][2 + h]);
            }
        }

        float C3[2][4];
        #pragma unroll
        for (int n2 = 0; n2 < 2; n2++) {
            float q0 = sb3[n2 * 8 + 2 * t], q1 = sb3[n2 * 8 + 2 * t + 1];
            C3[n2][0] = q0; C3[n2][1] = q1; C3[n2][2] = q0; C3[n2][3] = q1;
        }
        #pragma unroll
        for (int c = 0; c < 2; c++) {
            #pragma unroll
            for (int n2 = 0; n2 < 2; n2++) {
                uint2 wh = sW[(48 + c * 2 + n2) * 32 + lane];
                uint2 wl = sW[(52 + c * 2 + n2) * 32 + lane];
                mma16816(C3[n2], A3h[c], wh);
                mma16816(C3[n2], A3l[c], wh);
                mma16816(C3[n2], A3h[c], wl);
            }
        }

        int tile = it * 16384 + blockIdx.x * 8 + warp;
        int R  = tile * 16;
        int b  = R >> 9;
        int s0 = (R & 511) + g;
        int s1 = s0 + 8;
        float* outb = g_memT + (size_t)b * 8192;
        #pragma unroll
        for (int n2 = 0; n2 < 2; n2++) {
            int m0 = n2 * 8 + 2 * t;
            outb[m0 * 512 + s0]       = C3[n2][0];
            outb[(m0 + 1) * 512 + s0] = C3[n2][1];
            outb[m0 * 512 + s1]       = C3[n2][2];
            outb[(m0 + 1) * 512 + s1] = C3[n2][3];
        }
        __syncthreads();
    }
}

// ---------------------------------------------------------------------------
// Kernel 2: 128 threads / 4 warps per batch — R13 hot loop (coalesced
// transposed weights); wq moved from registers to a 2KB smem stage to cut
// register pressure (raises residency on this latency-bound kernel).
// ---------------------------------------------------------------------------
__device__ __forceinline__ float sigmoidf_(float x) {
    return 1.f / (1.f + __expf(-x));
}

__global__ void __launch_bounds__(128) step_kernel(
    const int*   __restrict__ lengths,
    const float* __restrict__ pb_,   // 16
    const float* __restrict__ b1,    // 32
    const float* __restrict__ b2,    // 32
    const float* __restrict__ b3,    // 64
    const float* __restrict__ esv_,  // 64
    float*       __restrict__ out)   // (B,64)
{
    __shared__ __align__(16) float memT[MM * SS];   // 32 KB [m*512+s]
    __shared__ float spw[32 * 16];                   // 2 KB pwT stage [k*16+m]
    __shared__ float qst[32];
    __shared__ float hst[32];
    __shared__ float red[8 + 64];
    __shared__ float x1s[32], x2s[32];
    __shared__ float gates[128];

    const unsigned FULL = 0xffffffffu;
    int b    = blockIdx.x;
    int tid  = threadIdx.x;
    int lane = tid & 31;
    int warp = tid >> 5;

    {
        const float4* gm = (const float4*)(g_memT + (size_t)b * (MM * SS));
        float4* dst = (float4*)memT;
        #pragma unroll
        for (int i = tid; i < 2048; i += 128) dst[i] = gm[i];
    }
    // coalesced smem stage of pwT
    #pragma unroll
    for (int i = tid; i < 512; i += 128) spw[i] = __ldg(g_pwT + i);
    if (tid < 32) qst[tid] = 0.f;

    int len  = lengths[b];
    int slen = (len > 0) ? len : 1;

    float bsr = g_bsum[tid];
    float c   = 0.f;

    // gate-weight column in registers (coalesced reads of g_whhT)
    float wg[32];
    #pragma unroll
    for (int k = 0; k < 32; k++) wg[k] = __ldg(g_whhT + k * 128 + tid);
    float pbr = pb_[tid & 15];
    __syncthreads();

    const float4* memT4 = (const float4*)memT;

    #pragma unroll 1
    for (int step = 0; step < NSTEPS; step++) {
        float ga = bsr;
        #pragma unroll
        for (int k = 0; k < 32; k++)
            ga = fmaf(qst[k], wg[k], ga);
        gates[tid] = ga;
        __syncthreads();

        if (tid < 32) {
            float ig = sigmoidf_(gates[tid]);
            float fg = sigmoidf_(gates[32 + tid]);
            float gg = tanhf(gates[64 + tid]);
            float og = sigmoidf_(gates[96 + tid]);
            c = fmaf(fg, c, ig * gg);
            hst[tid] = og * tanhf(c);
        }
        __syncthreads();

        if (tid < 16) {
            float aq = pbr;
            #pragma unroll
            for (int k = 0; k < 32; k++)
                aq = fmaf(hst[k], spw[k * 16 + tid], aq);
            qst[tid] = aq;
        }
        __syncthreads();

        int base = lane + 32 * warp;
        float4 acc = make_float4(0.f, 0.f, 0.f, 0.f);
        #pragma unroll
        for (int m = 0; m < 16; m++) {
            float4 v = memT4[m * 128 + base];
            float q = qst[m];
            acc.x = fmaf(q, v.x, acc.x);
            acc.y = fmaf(q, v.y, acc.y);
            acc.z = fmaf(q, v.z, acc.z);
            acc.w = fmaf(q, v.w, acc.w);
        }
        int s = 4 * lane + 128 * warp;
        if (s     >= slen) acc.x = -1e30f;
        if (s + 1 >= slen) acc.y = -1e30f;
        if (s + 2 >= slen) acc.z = -1e30f;
        if (s + 3 >= slen) acc.w = -1e30f;

        float mx = fmaxf(fmaxf(acc.x, acc.y), fmaxf(acc.z, acc.w));
        #pragma unroll
        for (int off = 16; off; off >>= 1)
            mx = fmaxf(mx, __shfl_xor_sync(FULL, mx, off));
        if (lane == 0) red[warp] = mx;
        __syncthreads();
        mx = fmaxf(fmaxf(red[0], red[1]), fmaxf(red[2], red[3]));

        float4 ex;
        ex.x = __expf(acc.x - mx);
        ex.y = __expf(acc.y - mx);
        ex.z = __expf(acc.z - mx);
        ex.w = __expf(acc.w - mx);
        float ssum = (ex.x + ex.y) + (ex.z + ex.w);
        #pragma unroll
        for (int off = 16; off; off >>= 1)
            ssum += __shfl_xor_sync(FULL, ssum, off);
        if (lane == 0) red[4 + warp] = ssum;

        float rm[16];
        #pragma unroll
        for (int m = 0; m < 16; m++) {
            float4 v = memT4[m * 128 + base];
            rm[m] = fmaf(ex.x, v.x, fmaf(ex.y, v.y, fmaf(ex.z, v.z, ex.w * v.w)));
        }
        #pragma unroll
        for (int m = 0; m < 16; m++) {
            #pragma unroll
            for (int off = 16; off; off >>= 1)
                rm[m] += __shfl_xor_sync(FULL, rm[m], off);
        }
        if (lane == 0) {
            #pragma unroll
            for (int m = 0; m < 16; m++) red[8 + warp * 16 + m] = rm[m];
        }
        __syncthreads();

        if (tid < 16) {
            float inv = 1.f / (((red[4] + red[5]) + (red[6] + red[7])));
            float rr = ((red[8 + tid] + red[24 + tid]) +
                        (red[40 + tid] + red[56 + tid]));
            qst[16 + tid] = rr * inv;
        }
        __syncthreads();
    }

    // ---- write MLP (coalesced transposed weights) ----
    if (tid < 32) {
        float acc = b1[tid];
        #pragma unroll
        for (int k = 0; k < 32; k++)
            acc = fmaf(qst[k], __ldg(g_w1T + k * 32 + tid), acc);
        x1s[tid] = fmaxf(acc, 0.f);
    }
    __syncthreads();
    if (tid < 32) {
        float acc = b2[tid];
        #pragma unroll
        for (int k = 0; k < 32; k++)
            acc = fmaf(x1s[k], __ldg(g_w2T + k * 32 + tid), acc);
        x2s[tid] = fmaxf(acc, 0.f);
    }
    __syncthreads();
    if (tid < 64) {
        float acc = b3[tid];
        #pragma unroll
        for (int k = 0; k < 32; k++)
            acc = fmaf(x2s[k], __ldg(g_w3T + k * 64 + tid), acc);
        out[(size_t)b * OUTD + tid] = (len > 0) ? acc : esv_[tid];
    }
}

// ---------------------------------------------------------------------------
extern "C" void kernel_launch(void* const* d_in, const int* in_sizes, int n_in,
                              void* d_out, int out_size)
{
    const float* input_set = (const float*)d_in[0];
    const int*   lengths   = (const int*)  d_in[1];
    const float* r_w1 = (const float*)d_in[2];
    const float* r_b1 = (const float*)d_in[3];
    const float* r_w2 = (const float*)d_in[4];
    const float* r_b2 = (const float*)d_in[5];
    const float* r_w3 = (const float*)d_in[6];
    const float* r_b3 = (const float*)d_in[7];
    // d_in[8] = lstm_wih (unused: LSTM input is identically zero)
    const float* lstm_whh = (const float*)d_in[9];
    const float* lstm_bih = (const float*)d_in[10];
    const float* lstm_bhh = (const float*)d_in[11];
    const float* proj_w   = (const float*)d_in[12];
    const float* proj_b   = (const float*)d_in[13];
    const float* w_w1 = (const float*)d_in[14];
    const float* w_b1 = (const float*)d_in[15];
    const float* w_w2 = (const float*)d_in[16];
    const float* w_b2 = (const float*)d_in[17];
    const float* w_w3 = (const float*)d_in[18];
    const float* w_b3 = (const float*)d_in[19];
    const float* esv  = (const float*)d_in[20];
    float* out = (float*)d_out;

    static int smem_set = 0;
    if (!smem_set) {
        cudaFuncSetAttribute(mem_mlp_kernel,
                             cudaFuncAttributeMaxDynamicSharedMemorySize,
                             SMEM_DYN);
        smem_set = 1;
    }

    prep_kernel<<<32, 128>>>(lstm_whh, lstm_bih, lstm_bhh, proj_w,
                             w_w1, w_w2, w_w3);

    mem_mlp_kernel<<<2048, 256, SMEM_DYN>>>(input_set,
                                            r_w1, r_b1, r_w2, r_b2, r_w3, r_b3);

    step_kernel<<<BB, 128>>>(lengths, proj_b, w_b1, w_b2, w_b3, esv, out);
}

// round 17
// speedup vs baseline: 1.3440x; 1.0512x over previous
#include <cuda_runtime.h>
#include <cuda_bf16.h>
#include <math.h>

#define BB 4096
#define SS 512
#define EE 64
#define MM 16
#define OUTD 64
#define NSTEPS 5

// Scratch: memories transposed per batch: g_memT[b*MM*SS + m*SS + s]
__device__ float g_memT[(size_t)BB * MM * SS];
// Pre-transposed small weights (k-major) for the recurrence phase
__device__ float g_whhT[32 * 128];   // [k][j]
__device__ float g_pwT [32 * 16];    // [k][m]
__device__ float g_w1T [32 * 32];    // [k][j]
__device__ float g_w2T [32 * 32];    // [k][j]
__device__ float g_w3T [32 * 64];    // [k][j]
__device__ float g_bsum[128];        // bih + bhh
// Precomputed bf16 B-fragments for the reading MLP (hi/lo split)
__device__ uint2 g_frags[56 * 32];

// ---------------- bf16 pack/split helpers ----------------
__device__ __forceinline__ unsigned int packbf(float lo, float hi) {
    __nv_bfloat162 p = __floats2bfloat162_rn(lo, hi);   // .x -> low 16 bits
    return *reinterpret_cast<unsigned int*>(&p);
}
__device__ __forceinline__ void split2(float v0, float v1,
                                       unsigned int& ph, unsigned int& pl) {
    ph = packbf(v0, v1);
    float f0 = __uint_as_float(ph << 16);
    float f1 = __uint_as_float(ph & 0xffff0000u);
    pl = packbf(v0 - f0, v1 - f1);
}

__device__ __forceinline__ void mma16816(float* c, const unsigned int* a, uint2 b) {
    asm("mma.sync.aligned.m16n8k16.row.col.f32.bf16.bf16.f32 "
        "{%0,%1,%2,%3}, {%4,%5,%6,%7}, {%8,%9}, {%0,%1,%2,%3};"
        : "+f"(c[0]), "+f"(c[1]), "+f"(c[2]), "+f"(c[3])
        : "r"(a[0]), "r"(a[1]), "r"(a[2]), "r"(a[3]), "r"(b.x), "r"(b.y));
}

// ---------------- cp.async helpers ----------------
__device__ __forceinline__ void cp_async16(void* smem_ptr, const void* gptr) {
    unsigned int saddr = (unsigned int)__cvta_generic_to_shared(smem_ptr);
    asm volatile("cp.async.cg.shared.global [%0], [%1], 16;"
                 :: "r"(saddr), "l"(gptr));
}
__device__ __forceinline__ void cp_commit() {
    asm volatile("cp.async.commit_group;");
}
template <int N>
__device__ __forceinline__ void cp_wait() {
    asm volatile("cp.async.wait_group %0;" :: "n"(N));
}

// ---------------------------------------------------------------------------
// Kernel 0: weight transposes + B-fragment construction (R13 version)
// ---------------------------------------------------------------------------
__device__ __forceinline__ uint2 make_bfrag(const float* __restrict__ w,
                                            int K, int n, int kbase, int t, int lo)
{
    float a0 = w[n * K + kbase + 2 * t];
    float a1 = w[n * K + kbase + 2 * t + 1];
    float a8 = w[n * K + kbase + 2 * t + 8];
    float a9 = w[n * K + kbase + 2 * t + 9];
    if (lo) {
        a0 -= __bfloat162float(__float2bfloat16(a0));
        a1 -= __bfloat162float(__float2bfloat16(a1));
        a8 -= __bfloat162float(__float2bfloat16(a8));
        a9 -= __bfloat162float(__float2bfloat16(a9));
    }
    uint2 r;
    r.x = packbf(a0, a1);
    r.y = packbf(a8, a9);
    return r;
}

__global__ void prep_kernel(
    const float* __restrict__ whh, const float* __restrict__ bih,
    const float* __restrict__ bhh, const float* __restrict__ pw,
    const float* __restrict__ w1,  const float* __restrict__ w2,
    const float* __restrict__ w3,
    const float* __restrict__ rw1, const float* __restrict__ rw2,
    const float* __restrict__ rw3)
{
    int gid = blockIdx.x * 128 + threadIdx.x;   // 4096 threads
    int nt  = gridDim.x * 128;
    for (int i = gid; i < 4096; i += nt) { int j = i >> 5, k = i & 31; g_whhT[k*128 + j] = whh[i]; }
    for (int i = gid; i < 512;  i += nt) { int m = i >> 5, k = i & 31; g_pwT [k*16  + m] = pw[i]; }
    for (int i = gid; i < 1024; i += nt) { int j = i >> 5, k = i & 31; g_w1T[k*32 + j] = w1[i];
                                           g_w2T[k*32 + j] = w2[i]; }
    for (int i = gid; i < 2048; i += nt) { int j = i >> 5, k = i & 31; g_w3T[k*64 + j] = w3[i]; }
    if (gid < 128) g_bsum[gid] = bih[gid] + bhh[gid];

    if (gid < 56 * 32) {
        int lane = gid & 31, fid = gid >> 5;
        int g = lane >> 2, t = lane & 3;
        uint2 f;
        if (fid < 32) {
            int lo = (fid >= 16);
            int c  = (fid & 15) >> 2, n4 = fid & 3;
            f = make_bfrag(rw1, 64, n4 * 8 + g, c * 16, t, lo);
        } else if (fid < 48) {
            int lo = (fid >= 40);
            int c  = ((fid - 32) & 7) >> 2, n4 = fid & 3;
            f = make_bfrag(rw2, 32, n4 * 8 + g, c * 16, t, lo);
        } else {
            int lo = (fid >= 52);
            int c  = ((fid - 48) & 3) >> 1, n2 = fid & 1;
            f = make_bfrag(rw3, 32, n2 * 8 + g, c * 16, t, lo);
        }
        g_frags[fid * 32 + lane] = f;
    }
}

// ---------------------------------------------------------------------------
// Kernel 1: reading MLP on tensor cores — exact R13 version (proven fastest).
// ---------------------------------------------------------------------------
#define XROW 68                       // padded smem row stride (floats)
#define XSTAGE (128 * XROW)           // floats per stage
#define SMEM_DYN (14336 + 384 + 2 * XSTAGE * 4)

__global__ void __launch_bounds__(256) mem_mlp_kernel(
    const float* __restrict__ x,
    const float* __restrict__ b1,
    const float* __restrict__ b2,
    const float* __restrict__ b3)
{
    extern __shared__ char dynsm[];
    uint2* sW  = (uint2*)dynsm;                       // 14336 B
    float* sb1 = (float*)(dynsm + 14336);             // 32
    float* sb2 = sb1 + 32;                            // 32
    float* sb3 = sb2 + 32;                            // 16
    float* xs  = (float*)(dynsm + 14336 + 384);       // 2 stages

    int tid = threadIdx.x;
    #pragma unroll
    for (int i = 0; i < 7; i++) ((uint2*)sW)[tid + i * 256] = g_frags[tid + i * 256];
    if (tid < 32) { sb1[tid] = b1[tid]; sb2[tid] = b2[tid]; }
    if (tid < 16) sb3[tid] = b3[tid];

    int lane = tid & 31, warp = tid >> 5;
    int g = lane >> 2, t = lane & 3;

    auto issue_stage = [&](int it) {
        size_t base_row = ((size_t)it * 16384 + blockIdx.x * 8) * 16;
        const float* gx = x + base_row * 64;
        float* dst = xs + (it & 1) * XSTAGE;
        #pragma unroll
        for (int i = tid; i < 2048; i += 256) {
            int r = i >> 4, cch = i & 15;
            cp_async16(dst + r * XROW + cch * 4, gx + r * 64 + cch * 4);
        }
        cp_commit();
    };

    issue_stage(0);
    __syncthreads();

    #pragma unroll 1
    for (int it = 0; it < 8; it++) {
        if (it + 1 < 8) {
            issue_stage(it + 1);
            cp_wait<1>();
        } else {
            cp_wait<0>();
        }
        __syncthreads();

        const float* xbuf = xs + (it & 1) * XSTAGE;
        const float* xr0 = xbuf + (warp * 16 + g) * XROW;
        const float* xr1 = xr0 + 8 * XROW;

        unsigned int Ah[4][4], Al[4][4];
        #pragma unroll
        for (int c = 0; c < 4; c++) {
            float2 v00 = *(const float2*)(xr0 + c * 16 + 2 * t);
            float2 v01 = *(const float2*)(xr0 + c * 16 + 2 * t + 8);
            float2 v10 = *(const float2*)(xr1 + c * 16 + 2 * t);
            float2 v11 = *(const float2*)(xr1 + c * 16 + 2 * t + 8);
            split2(v00.x, v00.y, Ah[c][0], Al[c][0]);
            split2(v10.x, v10.y, Ah[c][1], Al[c][1]);
            split2(v01.x, v01.y, Ah[c][2], Al[c][2]);
            split2(v11.x, v11.y, Ah[c][3], Al[c][3]);
        }

        float C1[4][4];
        #pragma unroll
        for (int n4 = 0; n4 < 4; n4++) {
            float q0 = sb1[n4 * 8 + 2 * t], q1 = sb1[n4 * 8 + 2 * t + 1];
            C1[n4][0] = q0; C1[n4][1] = q1; C1[n4][2] = q0; C1[n4][3] = q1;
        }
        #pragma unroll
        for (int c = 0; c < 4; c++) {
            #pragma unroll
            for (int n4 = 0; n4 < 4; n4++) {
                uint2 wh = sW[(c * 4 + n4) * 32 + lane];
                uint2 wl = sW[(16 + c * 4 + n4) * 32 + lane];
                mma16816(C1[n4], Ah[c], wh);
                mma16816(C1[n4], Al[c], wh);
                mma16816(C1[n4], Ah[c], wl);
            }
        }

        unsigned int A2h[2][4], A2l[2][4];
        #pragma unroll
        for (int cc = 0; cc < 2; cc++) {
            #pragma unroll
            for (int h = 0; h < 2; h++) {
                float p0 = fmaxf(C1[2*cc][2*h],     0.f);
                float p1 = fmaxf(C1[2*cc][2*h + 1], 0.f);
                split2(p0, p1, A2h[cc][h], A2l[cc][h]);
                float q0 = fmaxf(C1[2*cc+1][2*h],     0.f);
                float q1 = fmaxf(C1[2*cc+1][2*h + 1], 0.f);
                split2(q0, q1, A2h[cc][2 + h], A2l[cc][2 + h]);
            }
        }

        float C2[4][4];
        #pragma unroll
        for (int n4 = 0; n4 < 4; n4++) {
            float q0 = sb2[n4 * 8 + 2 * t], q1 = sb2[n4 * 8 + 2 * t + 1];
            C2[n4][0] = q0; C2[n4][1] = q1; C2[n4][2] = q0; C2[n4][3] = q1;
        }
        #pragma unroll
        for (int c = 0; c < 2; c++) {
            #pragma unroll
            for (int n4 = 0; n4 < 4; n4++) {
                uint2 wh = sW[(32 + c * 4 + n4) * 32 + lane];
                uint2 wl = sW[(40 + c * 4 + n4) * 32 + lane];
                mma16816(C2[n4], A2h[c], wh);
                mma16816(C2[n4], A2l[c], wh);
                mma16816(C2[n4], A2h[c], wl);
            }
        }

        unsigned int A3h[2][4], A3l[2][4];
        #pragma unroll
        for (int cc = 0; cc < 2; cc++) {
            #pragma unroll
            for (int h = 0; h < 2; h++) {
                float p0 = fmaxf(C2[2*cc][2*h],     0.f);
                float p1 = fmaxf(C2[2*cc][2*h + 1], 0.f);
                split2(p0, p1, A3h[cc][h], A3l[cc][h]);
                float q0 = fmaxf(C2[2*cc+1][2*h],     0.f);
                float q1 = fmaxf(C2[2*cc+1][2*h + 1], 0.f);
                split2(q0, q1, A3h[cc][2 + h], A3l[cc][2 + h]);
            }
        }

        float C3[2][4];
        #pragma unroll
        for (int n2 = 0; n2 < 2; n2++) {
            float q0 = sb3[n2 * 8 + 2 * t], q1 = sb3[n2 * 8 + 2 * t + 1];
            C3[n2][0] = q0; C3[n2][1] = q1; C3[n2][2] = q0; C3[n2][3] = q1;
        }
        #pragma unroll
        for (int c = 0; c < 2; c++) {
            #pragma unroll
            for (int n2 = 0; n2 < 2; n2++) {
                uint2 wh = sW[(48 + c * 2 + n2) * 32 + lane];
                uint2 wl = sW[(52 + c * 2 + n2) * 32 + lane];
                mma16816(C3[n2], A3h[c], wh);
                mma16816(C3[n2], A3l[c], wh);
                mma16816(C3[n2], A3h[c], wl);
            }
        }

        int tile = it * 16384 + blockIdx.x * 8 + warp;
        int R  = tile * 16;
        int b  = R >> 9;
        int s0 = (R & 511) + g;
        int s1 = s0 + 8;
        float* outb = g_memT + (size_t)b * 8192;
        #pragma unroll
        for (int n2 = 0; n2 < 2; n2++) {
            int m0 = n2 * 8 + 2 * t;
            outb[m0 * 512 + s0]       = C3[n2][0];
            outb[(m0 + 1) * 512 + s0] = C3[n2][1];
            outb[m0 * 512 + s1]       = C3[n2][2];
            outb[(m0 + 1) * 512 + s1] = C3[n2][3];
        }
        __syncthreads();
    }
}

// ---------------------------------------------------------------------------
// Kernel 2: 128 threads / 4 warps per batch. R13 hot loops; changes:
//  (a) wq -> 2KB smem stage (regs down, 5 CTAs/SM),
//  (b) LSTM + q fused in warp 0 via shuffles (one fewer barrier per step).
// ---------------------------------------------------------------------------
__device__ __forceinline__ float sigmoidf_(float x) {
    return 1.f / (1.f + __expf(-x));
}

__global__ void __launch_bounds__(128) step_kernel(
    const int*   __restrict__ lengths,
    const float* __restrict__ pb_,   // 16
    const float* __restrict__ b1,    // 32
    const float* __restrict__ b2,    // 32
    const float* __restrict__ b3,    // 64
    const float* __restrict__ esv_,  // 64
    float*       __restrict__ out)   // (B,64)
{
    __shared__ __align__(16) float memT[MM * SS];   // 32 KB [m*512+s]
    __shared__ float spw[32 * 16];                   // 2 KB pwT stage [k*16+m]
    __shared__ float qst[32];
    __shared__ float red[8 + 64];
    __shared__ float x1s[32], x2s[32];
    __shared__ float gates[128];

    const unsigned FULL = 0xffffffffu;
    int b    = blockIdx.x;
    int tid  = threadIdx.x;
    int lane = tid & 31;
    int warp = tid >> 5;

    {
        const float4* gm = (const float4*)(g_memT + (size_t)b * (MM * SS));
        float4* dst = (float4*)memT;
        #pragma unroll
        for (int i = tid; i < 2048; i += 128) dst[i] = gm[i];
    }
    #pragma unroll
    for (int i = tid; i < 512; i += 128) spw[i] = __ldg(g_pwT + i);
    if (tid < 32) qst[tid] = 0.f;

    int len  = lengths[b];
    int slen = (len > 0) ? len : 1;

    float bsr = g_bsum[tid];
    float c   = 0.f;

    // gate-weight column in registers (coalesced reads of g_whhT)
    float wg[32];
    #pragma unroll
    for (int k = 0; k < 32; k++) wg[k] = __ldg(g_whhT + k * 128 + tid);
    float pbr = pb_[tid & 15];
    __syncthreads();

    const float4* memT4 = (const float4*)memT;

    #pragma unroll 1
    for (int step = 0; step < NSTEPS; step++) {
        // ---- gates[tid] = bsum + sum_k qst[k] * whhT[k][tid] ----
        float ga = bsr;
        #pragma unroll
        for (int k = 0; k < 32; k++)
            ga = fmaf(qst[k], wg[k], ga);
        gates[tid] = ga;
        __syncthreads();                                         // B1

        // ---- LSTM + q projection fused in warp 0 (shuffles, no hst) ----
        if (warp == 0) {
            float ig = sigmoidf_(gates[lane]);
            float fg = sigmoidf_(gates[32 + lane]);
            float gg = tanhf(gates[64 + lane]);
            float og = sigmoidf_(gates[96 + lane]);
            c = fmaf(fg, c, ig * gg);
            float h = og * tanhf(c);

            float aq = pbr;
            int m = lane & 15;
            #pragma unroll
            for (int k = 0; k < 32; k++) {
                float hk = __shfl_sync(FULL, h, k);
                aq = fmaf(hk, spw[k * 16 + m], aq);
            }
            if (lane < 16) qst[lane] = aq;
        }
        __syncthreads();                                         // B2

        // ---- e for this warp's chunk: s = 4*lane + 128*warp ----
        int base = lane + 32 * warp;
        float4 acc = make_float4(0.f, 0.f, 0.f, 0.f);
        #pragma unroll
        for (int m = 0; m < 16; m++) {
            float4 v = memT4[m * 128 + base];
            float q = qst[m];
            acc.x = fmaf(q, v.x, acc.x);
            acc.y = fmaf(q, v.y, acc.y);
            acc.z = fmaf(q, v.z, acc.z);
            acc.w = fmaf(q, v.w, acc.w);
        }
        int s = 4 * lane + 128 * warp;
        if (s     >= slen) acc.x = -1e30f;
        if (s + 1 >= slen) acc.y = -1e30f;
        if (s + 2 >= slen) acc.z = -1e30f;
        if (s + 3 >= slen) acc.w = -1e30f;

        float mx = fmaxf(fmaxf(acc.x, acc.y), fmaxf(acc.z, acc.w));
        #pragma unroll
        for (int off = 16; off; off >>= 1)
            mx = fmaxf(mx, __shfl_xor_sync(FULL, mx, off));
        if (lane == 0) red[warp] = mx;
        __syncthreads();                                         // B3
        mx = fmaxf(fmaxf(red[0], red[1]), fmaxf(red[2], red[3]));

        float4 ex;
        ex.x = __expf(acc.x - mx);
        ex.y = __expf(acc.y - mx);
        ex.z = __expf(acc.z - mx);
        ex.w = __expf(acc.w - mx);
        float ssum = (ex.x + ex.y) + (ex.z + ex.w);
        #pragma unroll
        for (int off = 16; off; off >>= 1)
            ssum += __shfl_xor_sync(FULL, ssum, off);
        if (lane == 0) red[4 + warp] = ssum;

        float rm[16];
        #pragma unroll
        for (int m = 0; m < 16; m++) {
            float4 v = memT4[m * 128 + base];
            rm[m] = fmaf(ex.x, v.x, fmaf(ex.y, v.y, fmaf(ex.z, v.z, ex.w * v.w)));
        }
        #pragma unroll
        for (int m = 0; m < 16; m++) {
            #pragma unroll
            for (int off = 16; off; off >>= 1)
                rm[m] += __shfl_xor_sync(FULL, rm[m], off);
        }
        if (lane == 0) {
            #pragma unroll
            for (int m = 0; m < 16; m++) red[8 + warp * 16 + m] = rm[m];
        }
        __syncthreads();                                         // B4

        if (tid < 16) {
            float inv = 1.f / (((red[4] + red[5]) + (red[6] + red[7])));
            float rr = ((red[8 + tid] + red[24 + tid]) +
                        (red[40 + tid] + red[56 + tid]));
            qst[16 + tid] = rr * inv;
        }
        __syncthreads();                                         // B5
    }

    // ---- write MLP (coalesced transposed weights) ----
    if (tid < 32) {
        float acc = b1[tid];
        #pragma unroll
        for (int k = 0; k < 32; k++)
            acc = fmaf(qst[k], __ldg(g_w1T + k * 32 + tid), acc);
        x1s[tid] = fmaxf(acc, 0.f);
    }
    __syncthreads();
    if (tid < 32) {
        float acc = b2[tid];
        #pragma unroll
        for (int k = 0; k < 32; k++)
            acc = fmaf(x1s[k], __ldg(g_w2T + k * 32 + tid), acc);
        x2s[tid] = fmaxf(acc, 0.f);
    }
    __syncthreads();
    if (tid < 64) {
        float acc = b3[tid];
        #pragma unroll
        for (int k = 0; k < 32; k++)
            acc = fmaf(x2s[k], __ldg(g_w3T + k * 64 + tid), acc);
        out[(size_t)b * OUTD + tid] = (len > 0) ? acc : esv_[tid];
    }
}

// ---------------------------------------------------------------------------
extern "C" void kernel_launch(void* const* d_in, const int* in_sizes, int n_in,
                              void* d_out, int out_size)
{
    const float* input_set = (const float*)d_in[0];
    const int*   lengths   = (const int*)  d_in[1];
    const float* r_w1 = (const float*)d_in[2];
    const float* r_b1 = (const float*)d_in[3];
    const float* r_w2 = (const float*)d_in[4];
    const float* r_b2 = (const float*)d_in[5];
    const float* r_w3 = (const float*)d_in[6];
    const float* r_b3 = (const float*)d_in[7];
    // d_in[8] = lstm_wih (unused: LSTM input is identically zero)
    const float* lstm_whh = (const float*)d_in[9];
    const float* lstm_bih = (const float*)d_in[10];
    const float* lstm_bhh = (const float*)d_in[11];
    const float* proj_w   = (const float*)d_in[12];
    const float* proj_b   = (const float*)d_in[13];
    const float* w_w1 = (const float*)d_in[14];
    const float* w_b1 = (const float*)d_in[15];
    const float* w_w2 = (const float*)d_in[16];
    const float* w_b2 = (const float*)d_in[17];
    const float* w_w3 = (const float*)d_in[18];
    const float* w_b3 = (const float*)d_in[19];
    const float* esv  = (const float*)d_in[20];
    float* out = (float*)d_out;

    static int smem_set = 0;
    if (!smem_set) {
        cudaFuncSetAttribute(mem_mlp_kernel,
                             cudaFuncAttributeMaxDynamicSharedMemorySize,
                             SMEM_DYN);
        smem_set = 1;
    }

    prep_kernel<<<32, 128>>>(lstm_whh, lstm_bih, lstm_bhh, proj_w,
                             w_w1, w_w2, w_w3,
                             r_w1, r_w2, r_w3);

    mem_mlp_kernel<<<2048, 256, SMEM_DYN>>>(input_set, r_b1, r_b2, r_b3);

    step_kernel<<<BB, 128>>>(lengths, proj_b, w_b1, w_b2, w_b3, esv, out);
}